// round 1
// baseline (speedup 1.0000x reference)
#include <cuda_runtime.h>
#include <math.h>

#define Bsz  2
#define Ssz  2048
#define HIDs 2048
#define NHh  16
#define HDd  128
#define Mrows (Bsz*Ssz)   // 4096

// Scratch (allocation-free rule: __device__ globals)
__device__ float g_q[Mrows*HIDs];
__device__ float g_k[Mrows*HIDs];
__device__ float g_v[Mrows*HIDs];
__device__ float g_attn[Mrows*HIDs];

// ---------------------------------------------------------------------------
// SGEMM: C[M,N] = A[M,K] @ W[K,N] (+ bias[N]).  K = N = 2048 fixed.
// 128x128 block tile, BK=8, 256 threads, 8x8 per thread.
// ---------------------------------------------------------------------------
__global__ __launch_bounds__(256, 2)
void sgemm128(const float* __restrict__ A, const float* __restrict__ W,
              const float* __restrict__ bias, float* __restrict__ C)
{
    const int Kd = HIDs, Nd = HIDs;
    __shared__ float As[8][128];
    __shared__ float Bs[8][128];

    const int tid = threadIdx.x;
    const int bm = blockIdx.y * 128;
    const int bn = blockIdx.x * 128;

    const int arow = tid >> 1;            // 0..127
    const int acol = (tid & 1) << 2;      // 0 or 4
    const int brow = tid >> 5;            // 0..7
    const int bcol = (tid & 31) << 2;     // 0..124
    const int ty = tid >> 4;              // 0..15
    const int tx = tid & 15;              // 0..15

    float acc[8][8];
#pragma unroll
    for (int i = 0; i < 8; i++)
#pragma unroll
        for (int j = 0; j < 8; j++) acc[i][j] = 0.f;

    const float* Aptr = A + (size_t)(bm + arow) * Kd + acol;
    const float* Wptr = W + (size_t)brow * Nd + bn + bcol;

    for (int k0 = 0; k0 < Kd; k0 += 8) {
        float4 av = *(const float4*)(Aptr + k0);
        As[acol + 0][arow] = av.x;
        As[acol + 1][arow] = av.y;
        As[acol + 2][arow] = av.z;
        As[acol + 3][arow] = av.w;
        *(float4*)(&Bs[brow][bcol]) = *(const float4*)(Wptr + (size_t)k0 * Nd);
        __syncthreads();

#pragma unroll
        for (int k = 0; k < 8; k++) {
            float4 a0 = *(const float4*)(&As[k][ty * 8]);
            float4 a1 = *(const float4*)(&As[k][ty * 8 + 4]);
            float4 b0 = *(const float4*)(&Bs[k][tx * 8]);
            float4 b1 = *(const float4*)(&Bs[k][tx * 8 + 4]);
            float a[8] = {a0.x, a0.y, a0.z, a0.w, a1.x, a1.y, a1.z, a1.w};
            float b[8] = {b0.x, b0.y, b0.z, b0.w, b1.x, b1.y, b1.z, b1.w};
#pragma unroll
            for (int i = 0; i < 8; i++)
#pragma unroll
                for (int j = 0; j < 8; j++) acc[i][j] += a[i] * b[j];
        }
        __syncthreads();
    }

    float bz[8];
#pragma unroll
    for (int j = 0; j < 8; j++)
        bz[j] = bias ? bias[bn + tx * 8 + j] : 0.f;

#pragma unroll
    for (int i = 0; i < 8; i++) {
        const size_t row = (size_t)(bm + ty * 8 + i);
        float4 o0, o1;
        o0.x = acc[i][0] + bz[0]; o0.y = acc[i][1] + bz[1];
        o0.z = acc[i][2] + bz[2]; o0.w = acc[i][3] + bz[3];
        o1.x = acc[i][4] + bz[4]; o1.y = acc[i][5] + bz[5];
        o1.z = acc[i][6] + bz[6]; o1.w = acc[i][7] + bz[7];
        *(float4*)(&C[row * Nd + bn + tx * 8])     = o0;
        *(float4*)(&C[row * Nd + bn + tx * 8 + 4]) = o1;
    }
}

// ---------------------------------------------------------------------------
// RoPE (NeoX) applied in-place to g_q and g_k.
// One thread per (row m, head h, d in [0,64)).
// ---------------------------------------------------------------------------
__global__ void rope_kernel(float* __restrict__ q, float* __restrict__ k,
                            const int* __restrict__ positions)
{
    int idx = blockIdx.x * blockDim.x + threadIdx.x;
    if (idx >= Mrows * NHh * 64) return;
    int d  = idx & 63;
    int t  = idx >> 6;
    int h  = t % NHh;
    int m  = t / NHh;

    float pos = (float)positions[m];
    float invf = powf(10000.0f, -(float)d * (1.0f / 64.0f));
    float fr = pos * invf;
    float c = cosf(fr), s = sinf(fr);

    size_t base = (size_t)m * HIDs + h * HDd;
    float q1 = q[base + d], q2 = q[base + 64 + d];
    q[base + d]      = q1 * c - q2 * s;
    q[base + 64 + d] = q2 * c + q1 * s;
    float k1 = k[base + d], k2 = k[base + 64 + d];
    k[base + d]      = k1 * c - k2 * s;
    k[base + 64 + d] = k2 * c + k1 * s;
}

// ---------------------------------------------------------------------------
// Flash attention fp32, causal. One CTA = (b,h, 64 q-rows), 256 threads.
// Smem: Qs[64][132], Ks[64][130] (reused as P[64][65]), Vs[64][132].
// ---------------------------------------------------------------------------
#define QS_STR 132
#define KS_STR 130
#define VS_STR 132
#define PS_STR 65
#define QS_OFF 0
#define KS_OFF (64*QS_STR)
#define VS_OFF (KS_OFF + 64*KS_STR)
#define MR_OFF (VS_OFF + 64*VS_STR)
#define LR_OFF (MR_OFF + 64)
#define CR_OFF (LR_OFF + 64)
#define FLASH_SMEM_FLOATS (CR_OFF + 64)

__global__ __launch_bounds__(256, 2)
void flash_fp32(const float* __restrict__ Q, const float* __restrict__ Kg,
                const float* __restrict__ V, float* __restrict__ O)
{
    extern __shared__ float sm[];
    float* Qs   = sm + QS_OFF;
    float* Ks   = sm + KS_OFF;
    float* Ps   = Ks;                 // reuse after scores are consumed
    float* Vs   = sm + VS_OFF;
    float* mrow = sm + MR_OFF;
    float* lrow = sm + LR_OFF;
    float* crow = sm + CR_OFF;

    const int tid = threadIdx.x;
    const int bh = blockIdx.y;
    const int b  = bh / NHh;
    const int h  = bh % NHh;
    const int q0 = blockIdx.x * 64;
    const float SCALING = 0.08838834764831845f;   // 128^-0.5

    const size_t rowbase = (size_t)(b * Ssz) * HIDs + (size_t)h * HDd;

    // --- load Q tile (pre-scaled) ---
    {
        int r  = tid >> 5;
        int c4 = (tid & 31) << 2;
#pragma unroll
        for (int it = 0; it < 8; it++, r += 8) {
            float4 v = *(const float4*)(Q + rowbase + (size_t)(q0 + r) * HIDs + c4);
            Qs[r * QS_STR + c4 + 0] = v.x * SCALING;
            Qs[r * QS_STR + c4 + 1] = v.y * SCALING;
            Qs[r * QS_STR + c4 + 2] = v.z * SCALING;
            Qs[r * QS_STR + c4 + 3] = v.w * SCALING;
        }
    }
    if (tid < 64) { mrow[tid] = -INFINITY; lrow[tid] = 0.f; }

    float o[2][16];
#pragma unroll
    for (int i = 0; i < 16; i++) { o[0][i] = 0.f; o[1][i] = 0.f; }

    const int ro = tid >> 3;              // 0..31, owns rows {ro, ro+32}
    const int co = (tid & 7) << 2;        // owns cols {co, co+32, co+64, co+96} (x4)
    const int ty = tid >> 4, tx = tid & 15;
    const int ty4 = ty * 4, tx4 = tx * 4;

    const int ktmax = q0 >> 6;
    for (int kt = 0; kt <= ktmax; kt++) {
        const int k0 = kt << 6;
        __syncthreads();   // previous Ps/Vs fully consumed

        // --- load K (scalar-scattered, padded) and V (float4) tiles ---
        {
            int r  = tid >> 5;
            int c4 = (tid & 31) << 2;
#pragma unroll
            for (int it = 0; it < 8; it++, r += 8) {
                const size_t gro = rowbase + (size_t)(k0 + r) * HIDs + c4;
                float4 kv = *(const float4*)(Kg + gro);
                Ks[r * KS_STR + c4 + 0] = kv.x;
                Ks[r * KS_STR + c4 + 1] = kv.y;
                Ks[r * KS_STR + c4 + 2] = kv.z;
                Ks[r * KS_STR + c4 + 3] = kv.w;
                *(float4*)(Vs + r * VS_STR + c4) = *(const float4*)(V + gro);
            }
        }
        __syncthreads();

        // --- scores: 4x4 per thread over 64x64 tile ---
        float s[4][4];
#pragma unroll
        for (int i = 0; i < 4; i++)
#pragma unroll
            for (int j = 0; j < 4; j++) s[i][j] = 0.f;

#pragma unroll 2
        for (int d = 0; d < HDd; d += 4) {
            float4 a[4], bb[4];
#pragma unroll
            for (int i = 0; i < 4; i++)
                a[i] = *(const float4*)(Qs + (ty4 + i) * QS_STR + d);
#pragma unroll
            for (int j = 0; j < 4; j++) {
                float2 lo = *(const float2*)(Ks + (tx4 + j) * KS_STR + d);
                float2 hi = *(const float2*)(Ks + (tx4 + j) * KS_STR + d + 2);
                bb[j] = make_float4(lo.x, lo.y, hi.x, hi.y);
            }
#pragma unroll
            for (int i = 0; i < 4; i++)
#pragma unroll
                for (int j = 0; j < 4; j++)
                    s[i][j] += a[i].x * bb[j].x + a[i].y * bb[j].y +
                               a[i].z * bb[j].z + a[i].w * bb[j].w;
        }

        if (kt == ktmax) {     // diagonal tile: k0 == q0
#pragma unroll
            for (int i = 0; i < 4; i++)
#pragma unroll
                for (int j = 0; j < 4; j++)
                    if (tx4 + j > ty4 + i) s[i][j] = -INFINITY;
        }

        // --- streaming softmax stats (shfl across the 16 tx lanes) ---
        float mnew[4], cfac[4], rsum[4];
#pragma unroll
        for (int i = 0; i < 4; i++) {
            float rm = fmaxf(fmaxf(s[i][0], s[i][1]), fmaxf(s[i][2], s[i][3]));
#pragma unroll
            for (int off = 8; off >= 1; off >>= 1)
                rm = fmaxf(rm, __shfl_xor_sync(0xffffffffu, rm, off, 16));
            float mo = mrow[ty4 + i];
            float mn = fmaxf(mo, rm);
            mnew[i] = mn;
            cfac[i] = expf(mo - mn);
            float rs = 0.f;
#pragma unroll
            for (int j = 0; j < 4; j++) {
                float p = expf(s[i][j] - mn);
                s[i][j] = p;
                rs += p;
            }
#pragma unroll
            for (int off = 8; off >= 1; off >>= 1)
                rs += __shfl_xor_sync(0xffffffffu, rs, off, 16);
            rsum[i] = rs;
        }
        __syncthreads();   // all threads done reading Ks and mrow

        // --- P into shared (reusing Ks), stats update ---
#pragma unroll
        for (int i = 0; i < 4; i++)
#pragma unroll
            for (int j = 0; j < 4; j++)
                Ps[(ty4 + i) * PS_STR + tx4 + j] = s[i][j];
        if (tx == 0) {
#pragma unroll
            for (int i = 0; i < 4; i++) {
                int r = ty4 + i;
                mrow[r] = mnew[i];
                crow[r] = cfac[i];
                lrow[r] = lrow[r] * cfac[i] + rsum[i];
            }
        }
        __syncthreads();

        // --- O rescale + P @ V ---
        float c0 = crow[ro], c1 = crow[ro + 32];
#pragma unroll
        for (int i = 0; i < 16; i++) { o[0][i] *= c0; o[1][i] *= c1; }

#pragma unroll 4
        for (int kk = 0; kk < 64; kk++) {
            float p0 = Ps[ro * PS_STR + kk];
            float p1 = Ps[(ro + 32) * PS_STR + kk];
            const float* vrow = Vs + kk * VS_STR + co;
#pragma unroll
            for (int qq = 0; qq < 4; qq++) {
                float4 v4 = *(const float4*)(vrow + (qq << 5));
                o[0][qq * 4 + 0] += p0 * v4.x;
                o[0][qq * 4 + 1] += p0 * v4.y;
                o[0][qq * 4 + 2] += p0 * v4.z;
                o[0][qq * 4 + 3] += p0 * v4.w;
                o[1][qq * 4 + 0] += p1 * v4.x;
                o[1][qq * 4 + 1] += p1 * v4.y;
                o[1][qq * 4 + 2] += p1 * v4.z;
                o[1][qq * 4 + 3] += p1 * v4.w;
            }
        }
    }

    // --- epilogue: normalize and store ---
    float inv0 = 1.f / lrow[ro];
    float inv1 = 1.f / lrow[ro + 32];
    const size_t ob0 = rowbase + (size_t)(q0 + ro) * HIDs + co;
    const size_t ob1 = rowbase + (size_t)(q0 + ro + 32) * HIDs + co;
#pragma unroll
    for (int qq = 0; qq < 4; qq++) {
        float4 w0, w1;
        w0.x = o[0][qq*4+0]*inv0; w0.y = o[0][qq*4+1]*inv0;
        w0.z = o[0][qq*4+2]*inv0; w0.w = o[0][qq*4+3]*inv0;
        w1.x = o[1][qq*4+0]*inv1; w1.y = o[1][qq*4+1]*inv1;
        w1.z = o[1][qq*4+2]*inv1; w1.w = o[1][qq*4+3]*inv1;
        *(float4*)(O + ob0 + (qq << 5)) = w0;
        *(float4*)(O + ob1 + (qq << 5)) = w1;
    }
}

// ---------------------------------------------------------------------------
extern "C" void kernel_launch(void* const* d_in, const int* in_sizes, int n_in,
                              void* d_out, int out_size)
{
    (void)in_sizes; (void)n_in; (void)out_size;
    const float* hidden    = (const float*)d_in[0];
    const int*   positions = (const int*)  d_in[1];
    const float* wq = (const float*)d_in[2];
    const float* bq = (const float*)d_in[3];
    const float* wk = (const float*)d_in[4];
    const float* bk = (const float*)d_in[5];
    const float* wv = (const float*)d_in[6];
    const float* bv = (const float*)d_in[7];
    const float* wc = (const float*)d_in[8];
    float* out = (float*)d_out;

    float *qptr, *kptr, *vptr, *aptr;
    cudaGetSymbolAddress((void**)&qptr, g_q);
    cudaGetSymbolAddress((void**)&kptr, g_k);
    cudaGetSymbolAddress((void**)&vptr, g_v);
    cudaGetSymbolAddress((void**)&aptr, g_attn);

    dim3 gg(HIDs / 128, Mrows / 128);     // (16, 32)
    sgemm128<<<gg, 256>>>(hidden, wq, bq, qptr);
    sgemm128<<<gg, 256>>>(hidden, wk, bk, kptr);
    sgemm128<<<gg, 256>>>(hidden, wv, bv, vptr);

    rope_kernel<<<(Mrows * NHh * 64) / 256, 256>>>(qptr, kptr, positions);

    cudaFuncSetAttribute(flash_fp32, cudaFuncAttributeMaxDynamicSharedMemorySize,
                         FLASH_SMEM_FLOATS * 4);
    flash_fp32<<<dim3(Ssz / 64, Bsz * NHh), 256, FLASH_SMEM_FLOATS * 4>>>(
        qptr, kptr, vptr, aptr);

    sgemm128<<<gg, 256>>>(aptr, wc, nullptr, out);
}

// round 2
// speedup vs baseline: 3.5084x; 3.5084x over previous
#include <cuda_runtime.h>
#include <math.h>
#include <stdint.h>

#define Bsz  2
#define Ssz  2048
#define HIDs 2048
#define NHh  16
#define HDd  128
#define Mrows (Bsz*Ssz)   // 4096

// Scratch (__device__ globals per allocation rules)
__device__ float g_q[Mrows*HIDs];
__device__ float g_k[Mrows*HIDs];
__device__ float g_v[Mrows*HIDs];
__device__ float g_attn[Mrows*HIDs];
__device__ float g_hid[Mrows*HIDs];
__device__ float g_wq[HIDs*HIDs];
__device__ float g_wk[HIDs*HIDs];
__device__ float g_wv[HIDs*HIDs];
__device__ float g_wc[HIDs*HIDs];

// ---------------------------------------------------------------------------
// helpers
// ---------------------------------------------------------------------------
__device__ __forceinline__ float tf32r(float x) {
    uint32_t u;
    asm("cvt.rna.tf32.f32 %0, %1;" : "=r"(u) : "f"(x));
    return __uint_as_float(u);
}

__device__ __forceinline__ void mma8(float* c, const uint32_t* a, const uint32_t* b) {
    asm volatile(
        "mma.sync.aligned.m16n8k8.row.col.f32.tf32.tf32.f32 "
        "{%0,%1,%2,%3}, {%4,%5,%6,%7}, {%8,%9}, {%0,%1,%2,%3};"
        : "+f"(c[0]), "+f"(c[1]), "+f"(c[2]), "+f"(c[3])
        : "r"(a[0]), "r"(a[1]), "r"(a[2]), "r"(a[3]), "r"(b[0]), "r"(b[1]));
}

__device__ __forceinline__ void cp16(uint32_t saddr, const void* g) {
    asm volatile("cp.async.cg.shared.global [%0], [%1], 16;" :: "r"(saddr), "l"(g));
}

// ---------------------------------------------------------------------------
// tf32 pre-rounding pass (float4 elementwise)
// ---------------------------------------------------------------------------
__global__ void cvtk(const float* __restrict__ in, float* __restrict__ out, int n4) {
    int i = blockIdx.x * blockDim.x + threadIdx.x;
    if (i < n4) {
        float4 v = ((const float4*)in)[i];
        v.x = tf32r(v.x); v.y = tf32r(v.y);
        v.z = tf32r(v.z); v.w = tf32r(v.w);
        ((float4*)out)[i] = v;
    }
}

// ---------------------------------------------------------------------------
// TF32 tensor-core GEMM: C[M,N] = A[M,K] @ W[K,N] (+bias). K=N=2048.
// 128x128x32 tiles, 3-stage cp.async, 8 warps (4x2), warp tile 32x64.
// ---------------------------------------------------------------------------
#define AST 36     // As row stride (floats): mod32==4 -> conflict-free A frags
#define BST 136    // Bs row stride: mod32==8 -> conflict-free B frags
#define GSTAGE_F (128*AST + 32*BST)    // 8960 floats / stage
#define GSM_BYTES (3*GSTAGE_F*4)       // 107520 B

__global__ __launch_bounds__(256, 1)
void tgemm(const float* __restrict__ A, const float* __restrict__ W,
           const float* __restrict__ bias, float* __restrict__ C)
{
    extern __shared__ float sm[];
    const int tid = threadIdx.x;
    const int bm = blockIdx.y << 7, bn = blockIdx.x << 7;
    const int wid = tid >> 5, lane = tid & 31;
    const int wm = (wid & 3) << 5, wn = (wid >> 2) << 6;
    const int lr = lane >> 2, lc = lane & 3;

    float acc[2][8][4];
#pragma unroll
    for (int im = 0; im < 2; im++)
#pragma unroll
        for (int jn = 0; jn < 8; jn++)
#pragma unroll
            for (int t = 0; t < 4; t++) acc[im][jn][t] = 0.f;

    uint32_t smbase = (uint32_t)__cvta_generic_to_shared(sm);

#define G_ISSUE(st, k0)                                                        \
    {                                                                          \
        uint32_t abase = smbase + (st) * (GSTAGE_F * 4);                       \
        uint32_t bbase = abase + 128 * AST * 4;                                \
        _Pragma("unroll")                                                      \
        for (int i = 0; i < 4; i++) {                                          \
            int c = tid + (i << 8);                                            \
            int ar = c >> 3, ac = (c & 7) << 2;                                \
            cp16(abase + (ar * AST + ac) * 4,                                  \
                 A + (size_t)(bm + ar) * HIDs + (k0) + ac);                    \
            int br = c >> 5, bc = (c & 31) << 2;                               \
            cp16(bbase + (br * BST + bc) * 4,                                  \
                 W + (size_t)((k0) + br) * HIDs + bn + bc);                    \
        }                                                                      \
    }

    G_ISSUE(0, 0);
    asm volatile("cp.async.commit_group;");
    G_ISSUE(1, 32);
    asm volatile("cp.async.commit_group;");

    for (int it = 0; it < 64; it++) {
        asm volatile("cp.async.wait_group 1;");
        __syncthreads();
        if (it + 2 < 64) { G_ISSUE((it + 2) % 3, (it + 2) * 32); }
        asm volatile("cp.async.commit_group;");

        const float* as = sm + (it % 3) * GSTAGE_F;
        const float* bs = as + 128 * AST;
#pragma unroll
        for (int kk = 0; kk < 4; kk++) {
            uint32_t af[2][4];
            const int kc = (kk << 3) + lc;
#pragma unroll
            for (int im = 0; im < 2; im++) {
                int m = wm + (im << 4) + lr;
                af[im][0] = __float_as_uint(as[m * AST + kc]);
                af[im][1] = __float_as_uint(as[(m + 8) * AST + kc]);
                af[im][2] = __float_as_uint(as[m * AST + kc + 4]);
                af[im][3] = __float_as_uint(as[(m + 8) * AST + kc + 4]);
            }
#pragma unroll
            for (int jn = 0; jn < 8; jn++) {
                uint32_t bf[2];
                int col = wn + (jn << 3) + lr;
                bf[0] = __float_as_uint(bs[kc * BST + col]);
                bf[1] = __float_as_uint(bs[(kc + 4) * BST + col]);
                mma8(acc[0][jn], af[0], bf);
                mma8(acc[1][jn], af[1], bf);
            }
        }
    }

#pragma unroll
    for (int im = 0; im < 2; im++) {
        int row = bm + wm + (im << 4) + lr;
#pragma unroll
        for (int jn = 0; jn < 8; jn++) {
            int col = bn + wn + (jn << 3) + (lc << 1);
            float b0 = bias ? bias[col] : 0.f;
            float b1 = bias ? bias[col + 1] : 0.f;
            float2 v0 = make_float2(acc[im][jn][0] + b0, acc[im][jn][1] + b1);
            float2 v1 = make_float2(acc[im][jn][2] + b0, acc[im][jn][3] + b1);
            *(float2*)(C + (size_t)row * HIDs + col) = v0;
            *(float2*)(C + (size_t)(row + 8) * HIDs + col) = v1;
        }
    }
#undef G_ISSUE
}

// ---------------------------------------------------------------------------
// RoPE (NeoX) in-place on g_q, g_k
// ---------------------------------------------------------------------------
__global__ void rope_kernel(float* __restrict__ q, float* __restrict__ k,
                            const int* __restrict__ positions)
{
    int idx = blockIdx.x * blockDim.x + threadIdx.x;
    if (idx >= Mrows * NHh * 64) return;
    int d = idx & 63;
    int t = idx >> 6;
    int h = t % NHh;
    int m = t / NHh;

    float pos = (float)positions[m];
    float invf = powf(10000.0f, -(float)d * (1.0f / 64.0f));
    float fr = pos * invf;
    float c = cosf(fr), s = sinf(fr);

    size_t base = (size_t)m * HIDs + h * HDd;
    float q1 = q[base + d], q2 = q[base + 64 + d];
    q[base + d]      = q1 * c - q2 * s;
    q[base + 64 + d] = q2 * c + q1 * s;
    float k1 = k[base + d], k2 = k[base + 64 + d];
    k[base + d]      = k1 * c - k2 * s;
    k[base + 64 + d] = k2 * c + k1 * s;
}

// ---------------------------------------------------------------------------
// Flash attention, TF32 tensor cores. CTA = (b,h, 128 q rows), 8 warps x m16.
// k-tiles of 64. P routed through per-warp-private smem.
// ---------------------------------------------------------------------------
#define QST 132   // mod32==4: conflict-free A frags (8 rows x stride)
#define KST 132   // mod32==4: conflict-free QK B frags (8 n-rows x 4 k-cols)
#define VST 136   // mod32==8: conflict-free PV B frags (4 k-rows x 8 n-cols)
#define PST 68    // mod32==4: conflict-free PV A frags
#define FQ_OFF 0
#define FK_OFF (128*QST)
#define FV_OFF (FK_OFF + 64*KST)
#define FP_OFF (FV_OFF + 64*VST)
#define F_SMEMF (FP_OFF + 128*PST)    // 42752 floats = 171008 B

__global__ __launch_bounds__(256, 1)
void flash_tc(const float* __restrict__ Q, const float* __restrict__ Kg,
              const float* __restrict__ V, float* __restrict__ O)
{
    extern __shared__ float sm[];
    float* Qs = sm + FQ_OFF;
    float* Ks = sm + FK_OFF;
    float* Vs = sm + FV_OFF;
    float* Ps = sm + FP_OFF;

    const int tid = threadIdx.x;
    const int wid = tid >> 5, lane = tid & 31;
    const int lr = lane >> 2, lc = lane & 3;
    const int bh = blockIdx.y, b = bh / NHh, h = bh % NHh;
    const int q0 = blockIdx.x << 7;
    const int wrow = wid << 4;
    const float SC = 0.08838834764831845f;   // 128^-0.5
    const size_t rowbase = (size_t)(b * Ssz) * HIDs + (size_t)h * HDd;

    // stage Q (scaled + tf32-rounded)
#pragma unroll
    for (int i = 0; i < 16; i++) {
        int c = tid + (i << 8);
        int r = c >> 5, c4 = (c & 31) << 2;
        float4 v = *(const float4*)(Q + rowbase + (size_t)(q0 + r) * HIDs + c4);
        v.x = tf32r(v.x * SC); v.y = tf32r(v.y * SC);
        v.z = tf32r(v.z * SC); v.w = tf32r(v.w * SC);
        *(float4*)(Qs + r * QST + c4) = v;
    }

    float oacc[16][4];
#pragma unroll
    for (int nt = 0; nt < 16; nt++)
#pragma unroll
        for (int t = 0; t < 4; t++) oacc[nt][t] = 0.f;
    float m0 = -INFINITY, m1 = -INFINITY, l0 = 0.f, l1 = 0.f;

    const int ktmax = (q0 + 127) >> 6;
    for (int kt = 0; kt <= ktmax; kt++) {
        const int k0 = kt << 6;
        __syncthreads();                 // prior Ks/Vs fully consumed
#pragma unroll
        for (int i = 0; i < 8; i++) {
            int c = tid + (i << 8);
            int r = c >> 5, c4 = (c & 31) << 2;
            const size_t go = rowbase + (size_t)(k0 + r) * HIDs + c4;
            float4 kv = *(const float4*)(Kg + go);
            kv.x = tf32r(kv.x); kv.y = tf32r(kv.y);
            kv.z = tf32r(kv.z); kv.w = tf32r(kv.w);
            *(float4*)(Ks + r * KST + c4) = kv;
            float4 vv = *(const float4*)(V + go);
            vv.x = tf32r(vv.x); vv.y = tf32r(vv.y);
            vv.z = tf32r(vv.z); vv.w = tf32r(vv.w);
            *(float4*)(Vs + r * VST + c4) = vv;
        }
        __syncthreads();

        // ---- S = Q K^T (m16 x n64 x k128 per warp) ----
        float sacc[8][4];
#pragma unroll
        for (int jn = 0; jn < 8; jn++)
#pragma unroll
            for (int t = 0; t < 4; t++) sacc[jn][t] = 0.f;

#pragma unroll
        for (int kk = 0; kk < 16; kk++) {
            uint32_t af[4];
            const int qr = wrow + lr;
            const int kc = (kk << 3) + lc;
            af[0] = __float_as_uint(Qs[qr * QST + kc]);
            af[1] = __float_as_uint(Qs[(qr + 8) * QST + kc]);
            af[2] = __float_as_uint(Qs[qr * QST + kc + 4]);
            af[3] = __float_as_uint(Qs[(qr + 8) * QST + kc + 4]);
#pragma unroll
            for (int jn = 0; jn < 8; jn++) {
                uint32_t bf[2];
                int nr = (jn << 3) + lr;
                bf[0] = __float_as_uint(Ks[nr * KST + kc]);
                bf[1] = __float_as_uint(Ks[nr * KST + kc + 4]);
                mma8(sacc[jn], af, bf);
            }
        }

        // ---- causal mask ----
        const int rg0 = q0 + wrow + lr;
        if (k0 + 63 > q0 + wrow) {
#pragma unroll
            for (int jn = 0; jn < 8; jn++) {
                int cg = k0 + (jn << 3) + (lc << 1);
                if (cg > rg0)         sacc[jn][0] = -INFINITY;
                if (cg + 1 > rg0)     sacc[jn][1] = -INFINITY;
                if (cg > rg0 + 8)     sacc[jn][2] = -INFINITY;
                if (cg + 1 > rg0 + 8) sacc[jn][3] = -INFINITY;
            }
        }

        // ---- online softmax (rows rg0 and rg0+8; quad shuffles) ----
        float mx0 = -INFINITY, mx1 = -INFINITY;
#pragma unroll
        for (int jn = 0; jn < 8; jn++) {
            mx0 = fmaxf(mx0, fmaxf(sacc[jn][0], sacc[jn][1]));
            mx1 = fmaxf(mx1, fmaxf(sacc[jn][2], sacc[jn][3]));
        }
        mx0 = fmaxf(mx0, __shfl_xor_sync(0xffffffffu, mx0, 1));
        mx0 = fmaxf(mx0, __shfl_xor_sync(0xffffffffu, mx0, 2));
        mx1 = fmaxf(mx1, __shfl_xor_sync(0xffffffffu, mx1, 1));
        mx1 = fmaxf(mx1, __shfl_xor_sync(0xffffffffu, mx1, 2));

        float mn0 = fmaxf(m0, mx0), mn1 = fmaxf(m1, mx1);
        float cf0 = __expf(m0 - mn0), cf1 = __expf(m1 - mn1);
        float s0 = 0.f, s1 = 0.f;
#pragma unroll
        for (int jn = 0; jn < 8; jn++) {
            float p0 = __expf(sacc[jn][0] - mn0);
            float p1 = __expf(sacc[jn][1] - mn0);
            float p2 = __expf(sacc[jn][2] - mn1);
            float p3 = __expf(sacc[jn][3] - mn1);
            s0 += p0 + p1;
            s1 += p2 + p3;
            int pc = (jn << 3) + (lc << 1);
            *(float2*)(Ps + (wrow + lr) * PST + pc)     = make_float2(tf32r(p0), tf32r(p1));
            *(float2*)(Ps + (wrow + lr + 8) * PST + pc) = make_float2(tf32r(p2), tf32r(p3));
        }
        s0 += __shfl_xor_sync(0xffffffffu, s0, 1);
        s0 += __shfl_xor_sync(0xffffffffu, s0, 2);
        s1 += __shfl_xor_sync(0xffffffffu, s1, 1);
        s1 += __shfl_xor_sync(0xffffffffu, s1, 2);

        m0 = mn0; m1 = mn1;
        l0 = l0 * cf0 + s0;
        l1 = l1 * cf1 + s1;
        __syncwarp();    // order Ps writes vs cross-lane reads (warp-private tile)

        // ---- rescale O, then O += P V (m16 x n128 x k64 per warp) ----
#pragma unroll
        for (int nt = 0; nt < 16; nt++) {
            oacc[nt][0] *= cf0; oacc[nt][1] *= cf0;
            oacc[nt][2] *= cf1; oacc[nt][3] *= cf1;
        }
#pragma unroll
        for (int kk = 0; kk < 8; kk++) {
            uint32_t af[4];
            const int pr = wrow + lr;
            const int pc = (kk << 3) + lc;
            af[0] = __float_as_uint(Ps[pr * PST + pc]);
            af[1] = __float_as_uint(Ps[(pr + 8) * PST + pc]);
            af[2] = __float_as_uint(Ps[pr * PST + pc + 4]);
            af[3] = __float_as_uint(Ps[(pr + 8) * PST + pc + 4]);
#pragma unroll
            for (int nt = 0; nt < 16; nt++) {
                uint32_t bf[2];
                int vc = (nt << 3) + lr;
                bf[0] = __float_as_uint(Vs[((kk << 3) + lc) * VST + vc]);
                bf[1] = __float_as_uint(Vs[((kk << 3) + lc + 4) * VST + vc]);
                mma8(oacc[nt], af, bf);
            }
        }
    }

    // ---- epilogue: normalize, tf32-round (feeds final GEMM), store ----
    float i0 = 1.f / l0, i1 = 1.f / l1;
    const int row = q0 + wrow + lr;
#pragma unroll
    for (int nt = 0; nt < 16; nt++) {
        int col = (nt << 3) + (lc << 1);
        *(float2*)(O + rowbase + (size_t)row * HIDs + col) =
            make_float2(tf32r(oacc[nt][0] * i0), tf32r(oacc[nt][1] * i0));
        *(float2*)(O + rowbase + (size_t)(row + 8) * HIDs + col) =
            make_float2(tf32r(oacc[nt][2] * i1), tf32r(oacc[nt][3] * i1));
    }
}

// ---------------------------------------------------------------------------
extern "C" void kernel_launch(void* const* d_in, const int* in_sizes, int n_in,
                              void* d_out, int out_size)
{
    (void)in_sizes; (void)n_in; (void)out_size;
    const float* hidden    = (const float*)d_in[0];
    const int*   positions = (const int*)  d_in[1];
    const float* wq = (const float*)d_in[2];
    const float* bq = (const float*)d_in[3];
    const float* wk = (const float*)d_in[4];
    const float* bk = (const float*)d_in[5];
    const float* wv = (const float*)d_in[6];
    const float* bv = (const float*)d_in[7];
    const float* wc = (const float*)d_in[8];
    float* out = (float*)d_out;

    float *qp, *kp, *vp, *ap, *hp, *wqp, *wkp, *wvp, *wcp;
    cudaGetSymbolAddress((void**)&qp,  g_q);
    cudaGetSymbolAddress((void**)&kp,  g_k);
    cudaGetSymbolAddress((void**)&vp,  g_v);
    cudaGetSymbolAddress((void**)&ap,  g_attn);
    cudaGetSymbolAddress((void**)&hp,  g_hid);
    cudaGetSymbolAddress((void**)&wqp, g_wq);
    cudaGetSymbolAddress((void**)&wkp, g_wk);
    cudaGetSymbolAddress((void**)&wvp, g_wv);
    cudaGetSymbolAddress((void**)&wcp, g_wc);

    // tf32 pre-rounding (cp.async path copies raw bits)
    cvtk<<<(Mrows*HIDs/4 + 255)/256, 256>>>(hidden, hp, Mrows*HIDs/4);
    cvtk<<<(HIDs*HIDs/4 + 255)/256, 256>>>(wq, wqp, HIDs*HIDs/4);
    cvtk<<<(HIDs*HIDs/4 + 255)/256, 256>>>(wk, wkp, HIDs*HIDs/4);
    cvtk<<<(HIDs*HIDs/4 + 255)/256, 256>>>(wv, wvp, HIDs*HIDs/4);
    cvtk<<<(HIDs*HIDs/4 + 255)/256, 256>>>(wc, wcp, HIDs*HIDs/4);

    cudaFuncSetAttribute(tgemm, cudaFuncAttributeMaxDynamicSharedMemorySize, GSM_BYTES);
    dim3 gg(HIDs / 128, Mrows / 128);   // (16, 32)
    tgemm<<<gg, 256, GSM_BYTES>>>(hp, wqp, bq, qp);
    tgemm<<<gg, 256, GSM_BYTES>>>(hp, wkp, bk, kp);
    tgemm<<<gg, 256, GSM_BYTES>>>(hp, wvp, bv, vp);

    rope_kernel<<<(Mrows * NHh * 64) / 256, 256>>>(qp, kp, positions);

    cudaFuncSetAttribute(flash_tc, cudaFuncAttributeMaxDynamicSharedMemorySize,
                         F_SMEMF * 4);
    flash_tc<<<dim3(Ssz / 128, Bsz * NHh), 256, F_SMEMF * 4>>>(qp, kp, vp, ap);

    tgemm<<<gg, 256, GSM_BYTES>>>(ap, wcp, nullptr, out);
}

// round 6
// speedup vs baseline: 6.2312x; 1.7761x over previous
#include <cuda_runtime.h>
#include <cuda_fp16.h>
#include <math.h>
#include <stdint.h>

#define Bsz  2
#define Ssz  2048
#define HIDs 2048
#define NHh  16
#define HDd  128
#define Mrows (Bsz*Ssz)

__device__ __half g_hid[Mrows*HIDs];
__device__ __half g_q[Mrows*HIDs];
__device__ __half g_k[Mrows*HIDs];
__device__ __half g_v[Mrows*HIDs];
__device__ __half g_vt[Mrows*HIDs];     // [bh][d][s]
__device__ __half g_attn[Mrows*HIDs];
__device__ __half g_wq[HIDs*HIDs];      // [N][K]
__device__ __half g_wk[HIDs*HIDs];
__device__ __half g_wv[HIDs*HIDs];
__device__ __half g_wc[HIDs*HIDs];

__device__ __forceinline__ void mma16(float* c, const uint32_t* a, const uint32_t* b) {
    asm volatile(
        "mma.sync.aligned.m16n8k16.row.col.f32.f16.f16.f32 "
        "{%0,%1,%2,%3}, {%4,%5,%6,%7}, {%8,%9}, {%0,%1,%2,%3};"
        : "+f"(c[0]), "+f"(c[1]), "+f"(c[2]), "+f"(c[3])
        : "r"(a[0]), "r"(a[1]), "r"(a[2]), "r"(a[3]), "r"(b[0]), "r"(b[1]));
}
__device__ __forceinline__ void cp16(uint32_t saddr, const void* g) {
    asm volatile("cp.async.cg.shared.global [%0], [%1], 16;" :: "r"(saddr), "l"(g));
}
__device__ __forceinline__ uint32_t smem_u32(const void* p) {
    return (uint32_t)__cvta_generic_to_shared(p);
}
__device__ __forceinline__ uint32_t ex2h2(float x0, float x1) {
    __half2 h = __floats2half2_rn(x0, x1);
    uint32_t u = *reinterpret_cast<uint32_t*>(&h);
    uint32_t r;
    asm volatile("ex2.approx.f16x2 %0, %1;" : "=r"(r) : "r"(u));
    return r;
}

// ---------------- prep ----------------
__global__ void cvth(const float* __restrict__ in, __half* __restrict__ out, int n4) {
    int i = blockIdx.x * blockDim.x + threadIdx.x;
    if (i < n4) {
        float4 v = ((const float4*)in)[i];
        __half2 h0 = __floats2half2_rn(v.x, v.y);
        __half2 h1 = __floats2half2_rn(v.z, v.w);
        uint2 u;
        u.x = *reinterpret_cast<uint32_t*>(&h0);
        u.y = *reinterpret_cast<uint32_t*>(&h1);
        ((uint2*)out)[i] = u;
    }
}

__global__ void wtrh(const float* __restrict__ in, __half* __restrict__ out) {
    __shared__ float t[32][33];
    int bx = blockIdx.x << 5, by = blockIdx.y << 5;
#pragma unroll
    for (int i = 0; i < 4; i++) {
        int k = by + threadIdx.y + (i << 3);
        t[threadIdx.y + (i << 3)][threadIdx.x] = in[(size_t)k * HIDs + bx + threadIdx.x];
    }
    __syncthreads();
#pragma unroll
    for (int i = 0; i < 4; i++) {
        int n = bx + threadIdx.y + (i << 3);
        out[(size_t)n * HIDs + by + threadIdx.x] =
            __float2half(t[threadIdx.x][threadIdx.y + (i << 3)]);
    }
}

// v[b][s][h*128+d] -> vt[bh][d][s]
__global__ void vtrans(const __half* __restrict__ v, __half* __restrict__ vt) {
    __shared__ __half t[32][33];
    int bh = blockIdx.z;
    int b = bh >> 4, h = bh & 15;
    int s0 = blockIdx.x << 5, d0 = blockIdx.y << 5;
#pragma unroll
    for (int i = 0; i < 4; i++) {
        int s = s0 + threadIdx.y + (i << 3);
        t[threadIdx.y + (i << 3)][threadIdx.x] =
            v[((size_t)(b * Ssz + s)) * HIDs + h * HDd + d0 + threadIdx.x];
    }
    __syncthreads();
#pragma unroll
    for (int i = 0; i < 4; i++) {
        int d = d0 + threadIdx.y + (i << 3);
        vt[((size_t)bh * HDd + d) * Ssz + s0 + threadIdx.x] =
            t[threadIdx.x][threadIdx.y + (i << 3)];
    }
}

// ---------------- fp16 GEMM: C = A[M,K] @ Bt[N,K]^T (+bias) ----------------
#define GST 40
#define G_STAGE_H (2*128*GST)
#define G_SMEM (4*G_STAGE_H*2)

__global__ __launch_bounds__(256, 2)
void tgemm_h(const __half* __restrict__ A, const __half* __restrict__ Bt,
             const float* __restrict__ bias, void* __restrict__ Cout, int out_half)
{
    extern __shared__ __half gsm[];
    uint32_t smb = smem_u32(gsm);
    const int tid = threadIdx.x;
    const int wid = tid >> 5, lane = tid & 31;
    const int lr = lane >> 2, lc = lane & 3;
    const int bm = blockIdx.y << 7, bn = blockIdx.x << 7;
    const int wm = (wid & 3) << 5, wn = (wid >> 2) << 6;

    float acc[2][8][4];
#pragma unroll
    for (int im = 0; im < 2; im++)
#pragma unroll
        for (int jn = 0; jn < 8; jn++)
#pragma unroll
            for (int t = 0; t < 4; t++) acc[im][jn][t] = 0.f;

#define GLOAD(st, ch)                                                          \
    {                                                                          \
        uint32_t ab = smb + (st) * (G_STAGE_H * 2);                            \
        uint32_t bb = ab + 128 * GST * 2;                                      \
        _Pragma("unroll")                                                      \
        for (int i = 0; i < 2; i++) {                                          \
            int idx = tid + (i << 8);                                          \
            int r = idx >> 2, c = idx & 3;                                     \
            cp16(ab + r * 80 + c * 16,                                         \
                 A + (size_t)(bm + r) * HIDs + (ch) * 32 + c * 8);             \
            cp16(bb + r * 80 + c * 16,                                         \
                 Bt + (size_t)(bn + r) * HIDs + (ch) * 32 + c * 8);            \
        }                                                                      \
        asm volatile("cp.async.commit_group;");                                \
    }

    GLOAD(0, 0);
    GLOAD(1, 1);
    GLOAD(2, 2);

    for (int it = 0; it < 64; it++) {
        asm volatile("cp.async.wait_group 2;");
        __syncthreads();
        if (it + 3 < 64) {
            GLOAD((it + 3) & 3, it + 3);
        } else {
            asm volatile("cp.async.commit_group;");
        }

        const __half* as = gsm + (it & 3) * G_STAGE_H;
        const __half* bs = as + 128 * GST;
#pragma unroll
        for (int kk = 0; kk < 2; kk++) {
            const int kc = (kk << 4) + (lc << 1);
            uint32_t af[2][4];
#pragma unroll
            for (int im = 0; im < 2; im++) {
                int m = wm + (im << 4) + lr;
                af[im][0] = *(const uint32_t*)(as + m * GST + kc);
                af[im][1] = *(const uint32_t*)(as + (m + 8) * GST + kc);
                af[im][2] = *(const uint32_t*)(as + m * GST + kc + 8);
                af[im][3] = *(const uint32_t*)(as + (m + 8) * GST + kc + 8);
            }
#pragma unroll
            for (int jn = 0; jn < 8; jn++) {
                int n = wn + (jn << 3) + lr;
                uint32_t bf[2];
                bf[0] = *(const uint32_t*)(bs + n * GST + kc);
                bf[1] = *(const uint32_t*)(bs + n * GST + kc + 8);
                mma16(acc[0][jn], af[0], bf);
                mma16(acc[1][jn], af[1], bf);
            }
        }
    }
#undef GLOAD

#pragma unroll
    for (int im = 0; im < 2; im++) {
        int row = bm + wm + (im << 4) + lr;
#pragma unroll
        for (int jn = 0; jn < 8; jn++) {
            int col = bn + wn + (jn << 3) + (lc << 1);
            float b0 = bias ? bias[col] : 0.f;
            float b1 = bias ? bias[col + 1] : 0.f;
            float v0 = acc[im][jn][0] + b0, v1 = acc[im][jn][1] + b1;
            float v2 = acc[im][jn][2] + b0, v3 = acc[im][jn][3] + b1;
            if (out_half) {
                __half* C = (__half*)Cout;
                *(__half2*)(C + (size_t)row * HIDs + col) = __floats2half2_rn(v0, v1);
                *(__half2*)(C + (size_t)(row + 8) * HIDs + col) = __floats2half2_rn(v2, v3);
            } else {
                float* C = (float*)Cout;
                *(float2*)(C + (size_t)row * HIDs + col) = make_float2(v0, v1);
                *(float2*)(C + (size_t)(row + 8) * HIDs + col) = make_float2(v2, v3);
            }
        }
    }
}

// ---------------- RoPE (q also pre-scaled by 128^-0.5) ----------------
__global__ void rope_h(__half* __restrict__ q, __half* __restrict__ k,
                       const int* __restrict__ positions)
{
    int idx = blockIdx.x * blockDim.x + threadIdx.x;
    if (idx >= Mrows * NHh * 64) return;
    int d = idx & 63;
    int t = idx >> 6;
    int h = t % NHh;
    int m = t / NHh;
    const float SC = 0.08838834764831845f;

    float pos = (float)positions[m];
    float invf = powf(10000.0f, -(float)d * (1.0f / 64.0f));
    float fr = pos * invf;
    float c = cosf(fr), s = sinf(fr);

    size_t base = (size_t)m * HIDs + h * HDd;
    float q1 = __half2float(q[base + d]), q2 = __half2float(q[base + 64 + d]);
    q[base + d]      = __float2half((q1 * c - q2 * s) * SC);
    q[base + 64 + d] = __float2half((q2 * c + q1 * s) * SC);
    float k1 = __half2float(k[base + d]), k2 = __half2float(k[base + 64 + d]);
    k[base + d]      = __float2half(k1 * c - k2 * s);
    k[base + 64 + d] = __float2half(k2 * c + k1 * s);
}

// ---------------- flash attention fp16 ----------------
// CTA = (b,h, 128 q rows), 8 warps x m16, k-tile 64, single K/V buffer,
// l via ones-column (17th n-tile of V^T).
#define QS_OFF 0                       // 128 x (stride 136)
#define KS_OFF 17408                   // 64 x (stride 136)
#define VT_OFF 26112                   // 136 x (stride 72)
#define PS_OFF 35904                   // 128 x (stride 72)
#define F_HALFS 45120                  // 90240 B

__global__ __launch_bounds__(256, 1)
void flash_h(const __half* __restrict__ Q, const __half* __restrict__ K,
             const __half* __restrict__ Vt, __half* __restrict__ O)
{
    extern __shared__ __half fsm[];
    __half* Qs = fsm + QS_OFF;
    __half* Ks = fsm + KS_OFF;
    __half* Vs = fsm + VT_OFF;
    __half* Ps = fsm + PS_OFF;
    uint32_t smb = smem_u32(fsm);

    const int tid = threadIdx.x;
    const int wid = tid >> 5, lane = tid & 31;
    const int lr = lane >> 2, lc = lane & 3;
    const int bh = blockIdx.y, b = bh >> 4, h = bh & 15;
    const int q0 = blockIdx.x << 7;
    const int wrow = wid << 4;
    const int nkt = (q0 >> 6) + 2;
    const float L2E = 1.44269504f;
    const size_t qbase = (size_t)(b * Ssz) * HIDs + (size_t)h * HDd;
    const size_t vtbase = (size_t)bh * HDd * Ssz;

    // ones/zeros rows 128..135 of the Vt tile (cols 0..71), written once
    for (int i = tid; i < 8 * 72; i += 256) {
        int rr = i / 72, cc = i % 72;
        Vs[(128 + rr) * 72 + cc] = (rr == 0 && cc < 64) ? __float2half(1.f)
                                                        : __float2half(0.f);
    }

    // stage Q
#pragma unroll
    for (int i = 0; i < 8; i++) {
        int idx = tid + (i << 8);
        int r = idx >> 4, c = idx & 15;
        cp16(smb + r * 272 + c * 16, Q + qbase + (size_t)(q0 + r) * HIDs + c * 8);
    }
    asm volatile("cp.async.commit_group;");
    asm volatile("cp.async.wait_group 0;");
    __syncthreads();

    uint32_t qf[8][4];
#pragma unroll
    for (int kk = 0; kk < 8; kk++) {
        int r0 = wrow + lr;
        int c0 = (kk << 4) + (lc << 1);
        qf[kk][0] = *(const uint32_t*)(Qs + r0 * 136 + c0);
        qf[kk][1] = *(const uint32_t*)(Qs + (r0 + 8) * 136 + c0);
        qf[kk][2] = *(const uint32_t*)(Qs + r0 * 136 + c0 + 8);
        qf[kk][3] = *(const uint32_t*)(Qs + (r0 + 8) * 136 + c0 + 8);
    }

    float oacc[17][4];
#pragma unroll
    for (int nt = 0; nt < 17; nt++)
#pragma unroll
        for (int t = 0; t < 4; t++) oacc[nt][t] = 0.f;
    float m0 = -1e30f, m1 = -1e30f;

    for (int kt = 0; kt < nkt; kt++) {
        const int k0 = kt << 6;
        __syncthreads();
        // load K tile [64 x 128] and Vt tile [128 x 64]
#pragma unroll
        for (int i = 0; i < 4; i++) {
            int idx = tid + (i << 8);
            int r = idx >> 4, c = idx & 15;
            cp16(smb + KS_OFF * 2 + r * 272 + c * 16,
                 K + qbase + (size_t)(k0 + r) * HIDs + c * 8);
            int r2 = idx >> 3, c2 = idx & 7;
            cp16(smb + VT_OFF * 2 + r2 * 144 + c2 * 16,
                 Vt + vtbase + (size_t)r2 * Ssz + k0 + c2 * 8);
        }
        asm volatile("cp.async.commit_group;");
        asm volatile("cp.async.wait_group 0;");
        __syncthreads();

        // S = Q K^T : m16 x n64 x k128
        float sacc[8][4];
#pragma unroll
        for (int jn = 0; jn < 8; jn++)
#pragma unroll
            for (int t = 0; t < 4; t++) sacc[jn][t] = 0.f;
#pragma unroll
        for (int kk = 0; kk < 8; kk++) {
            const int kc = (kk << 4) + (lc << 1);
#pragma unroll
            for (int jn = 0; jn < 8; jn++) {
                int n = (jn << 3) + lr;
                uint32_t bf[2];
                bf[0] = *(const uint32_t*)(Ks + n * 136 + kc);
                bf[1] = *(const uint32_t*)(Ks + n * 136 + kc + 8);
                mma16(sacc[jn], qf[kk], bf);
            }
        }

        // causal mask
        const int rg0 = q0 + wrow + lr;
        if (k0 + 63 > q0 + wrow) {
#pragma unroll
            for (int jn = 0; jn < 8; jn++) {
                int cg = k0 + (jn << 3) + (lc << 1);
                if (cg > rg0)         sacc[jn][0] = -1e30f;
                if (cg + 1 > rg0)     sacc[jn][1] = -1e30f;
                if (cg > rg0 + 8)     sacc[jn][2] = -1e30f;
                if (cg + 1 > rg0 + 8) sacc[jn][3] = -1e30f;
            }
        }

        // row max
        float mx0 = -1e30f, mx1 = -1e30f;
#pragma unroll
        for (int jn = 0; jn < 8; jn++) {
            mx0 = fmaxf(mx0, fmaxf(sacc[jn][0], sacc[jn][1]));
            mx1 = fmaxf(mx1, fmaxf(sacc[jn][2], sacc[jn][3]));
        }
        mx0 = fmaxf(mx0, __shfl_xor_sync(0xffffffffu, mx0, 1));
        mx0 = fmaxf(mx0, __shfl_xor_sync(0xffffffffu, mx0, 2));
        mx1 = fmaxf(mx1, __shfl_xor_sync(0xffffffffu, mx1, 1));
        mx1 = fmaxf(mx1, __shfl_xor_sync(0xffffffffu, mx1, 2));

        if (mx0 > m0 || mx1 > m1) {
            float mn0 = fmaxf(m0, mx0), mn1 = fmaxf(m1, mx1);
            float cf0 = exp2f((m0 - mn0) * L2E);
            float cf1 = exp2f((m1 - mn1) * L2E);
#pragma unroll
            for (int nt = 0; nt < 17; nt++) {
                oacc[nt][0] *= cf0; oacc[nt][1] *= cf0;
                oacc[nt][2] *= cf1; oacc[nt][3] *= cf1;
            }
            m0 = mn0; m1 = mn1;
        }

        // P = exp2((s-m)*log2e) via f16x2 MUFU, straight to smem
        const float mls0 = m0 * L2E, mls1 = m1 * L2E;
        const int pr = wrow + lr;
#pragma unroll
        for (int jn = 0; jn < 8; jn++) {
            int pc = (jn << 3) + (lc << 1);
            uint32_t p01 = ex2h2(fmaf(sacc[jn][0], L2E, -mls0),
                                 fmaf(sacc[jn][1], L2E, -mls0));
            uint32_t p23 = ex2h2(fmaf(sacc[jn][2], L2E, -mls1),
                                 fmaf(sacc[jn][3], L2E, -mls1));
            *(uint32_t*)(Ps + pr * 72 + pc) = p01;
            *(uint32_t*)(Ps + (pr + 8) * 72 + pc) = p23;
        }
        __syncwarp();

        // O += P V^T : m16 x n136 x k64 (n-tile 16 accumulates l)
#pragma unroll
        for (int kk = 0; kk < 4; kk++) {
            const int kc = (kk << 4) + (lc << 1);
            uint32_t af[4];
            af[0] = *(const uint32_t*)(Ps + pr * 72 + kc);
            af[1] = *(const uint32_t*)(Ps + (pr + 8) * 72 + kc);
            af[2] = *(const uint32_t*)(Ps + pr * 72 + kc + 8);
            af[3] = *(const uint32_t*)(Ps + (pr + 8) * 72 + kc + 8);
#pragma unroll
            for (int nt = 0; nt < 17; nt++) {
                int n = (nt << 3) + lr;
                uint32_t bf[2];
                bf[0] = *(const uint32_t*)(Vs + n * 72 + kc);
                bf[1] = *(const uint32_t*)(Vs + n * 72 + kc + 8);
                mma16(oacc[nt], af, bf);
            }
        }
    }

    // l lives in oacc[16][0]/[2] at lanes lc==0 (col 128)
    float l0 = __shfl_sync(0xffffffffu, oacc[16][0], lane & 28);
    float l1 = __shfl_sync(0xffffffffu, oacc[16][2], lane & 28);
    float i0 = 1.f / l0, i1 = 1.f / l1;
    const int row = q0 + wrow + lr;
#pragma unroll
    for (int nt = 0; nt < 16; nt++) {
        int col = (nt << 3) + (lc << 1);
        *(__half2*)(O + qbase + (size_t)row * HIDs + col) =
            __floats2half2_rn(oacc[nt][0] * i0, oacc[nt][1] * i0);
        *(__half2*)(O + qbase + (size_t)(row + 8) * HIDs + col) =
            __floats2half2_rn(oacc[nt][2] * i1, oacc[nt][3] * i1);
    }
}

// ---------------------------------------------------------------------------
extern "C" void kernel_launch(void* const* d_in, const int* in_sizes, int n_in,
                              void* d_out, int out_size)
{
    (void)in_sizes; (void)n_in; (void)out_size;
    const float* hidden    = (const float*)d_in[0];
    const int*   positions = (const int*)  d_in[1];
    const float* wq = (const float*)d_in[2];
    const float* bq = (const float*)d_in[3];
    const float* wk = (const float*)d_in[4];
    const float* bk = (const float*)d_in[5];
    const float* wv = (const float*)d_in[6];
    const float* bv = (const float*)d_in[7];
    const float* wc = (const float*)d_in[8];
    float* out = (float*)d_out;

    __half *hp, *qp, *kp, *vp, *vtp, *ap, *wqp, *wkp, *wvp, *wcp;
    cudaGetSymbolAddress((void**)&hp,  g_hid);
    cudaGetSymbolAddress((void**)&qp,  g_q);
    cudaGetSymbolAddress((void**)&kp,  g_k);
    cudaGetSymbolAddress((void**)&vp,  g_v);
    cudaGetSymbolAddress((void**)&vtp, g_vt);
    cudaGetSymbolAddress((void**)&ap,  g_attn);
    cudaGetSymbolAddress((void**)&wqp, g_wq);
    cudaGetSymbolAddress((void**)&wkp, g_wk);
    cudaGetSymbolAddress((void**)&wvp, g_wv);
    cudaGetSymbolAddress((void**)&wcp, g_wc);

    cvth<<<(Mrows*HIDs/4 + 255)/256, 256>>>(hidden, hp, Mrows*HIDs/4);
    dim3 tg(HIDs/32, HIDs/32);
    wtrh<<<tg, dim3(32, 8)>>>(wq, wqp);
    wtrh<<<tg, dim3(32, 8)>>>(wk, wkp);
    wtrh<<<tg, dim3(32, 8)>>>(wv, wvp);
    wtrh<<<tg, dim3(32, 8)>>>(wc, wcp);

    cudaFuncSetAttribute(tgemm_h, cudaFuncAttributeMaxDynamicSharedMemorySize, G_SMEM);
    dim3 gg(HIDs / 128, Mrows / 128);   // (16, 32)
    tgemm_h<<<gg, 256, G_SMEM>>>(hp, wqp, bq, qp, 1);
    tgemm_h<<<gg, 256, G_SMEM>>>(hp, wkp, bk, kp, 1);
    tgemm_h<<<gg, 256, G_SMEM>>>(hp, wvp, bv, vp, 1);

    rope_h<<<(Mrows * NHh * 64) / 256, 256>>>(qp, kp, positions);
    vtrans<<<dim3(Ssz/32, HDd/32, Bsz*NHh), dim3(32, 8)>>>(vp, vtp);

    cudaFuncSetAttribute(flash_h, cudaFuncAttributeMaxDynamicSharedMemorySize,
                         F_HALFS * 2);
    flash_h<<<dim3(Ssz / 128, Bsz * NHh), 256, F_HALFS * 2>>>(qp, kp, vtp, ap);

    tgemm_h<<<gg, 256, G_SMEM>>>(ap, wcp, nullptr, out, 0);
}

// round 9
// speedup vs baseline: 6.6160x; 1.0618x over previous
#include <cuda_runtime.h>
#include <cuda_fp16.h>
#include <math.h>
#include <stdint.h>

#define Bsz  2
#define Ssz  2048
#define HIDs 2048
#define NHh  16
#define HDd  128
#define Mrows (Bsz*Ssz)

__device__ __half g_hid[Mrows*HIDs];
__device__ __half g_q[Mrows*HIDs];
__device__ __half g_k[Mrows*HIDs];
__device__ __half g_v[Mrows*HIDs];
__device__ __half g_vt[Mrows*HIDs];     // [bh][d][s]
__device__ __half g_attn[Mrows*HIDs];
__device__ __half g_wq[HIDs*HIDs];      // [N][K]
__device__ __half g_wk[HIDs*HIDs];
__device__ __half g_wv[HIDs*HIDs];
__device__ __half g_wc[HIDs*HIDs];

__device__ __forceinline__ void mma16(float* c, const uint32_t* a, const uint32_t* b) {
    asm volatile(
        "mma.sync.aligned.m16n8k16.row.col.f32.f16.f16.f32 "
        "{%0,%1,%2,%3}, {%4,%5,%6,%7}, {%8,%9}, {%0,%1,%2,%3};"
        : "+f"(c[0]), "+f"(c[1]), "+f"(c[2]), "+f"(c[3])
        : "r"(a[0]), "r"(a[1]), "r"(a[2]), "r"(a[3]), "r"(b[0]), "r"(b[1]));
}
__device__ __forceinline__ void cp16(uint32_t saddr, const void* g) {
    asm volatile("cp.async.cg.shared.global [%0], [%1], 16;" :: "r"(saddr), "l"(g));
}
__device__ __forceinline__ uint32_t smem_u32(const void* p) {
    return (uint32_t)__cvta_generic_to_shared(p);
}
__device__ __forceinline__ uint32_t ex2h2(float x0, float x1) {
    __half2 h = __floats2half2_rn(x0, x1);
    uint32_t u = *reinterpret_cast<uint32_t*>(&h);
    uint32_t r;
    asm volatile("ex2.approx.f16x2 %0, %1;" : "=r"(r) : "r"(u));
    return r;
}

// ---------------- prep ----------------
__global__ void cvth(const float* __restrict__ in, __half* __restrict__ out, int n4) {
    int i = blockIdx.x * blockDim.x + threadIdx.x;
    if (i < n4) {
        float4 v = ((const float4*)in)[i];
        __half2 h0 = __floats2half2_rn(v.x, v.y);
        __half2 h1 = __floats2half2_rn(v.z, v.w);
        uint2 u;
        u.x = *reinterpret_cast<uint32_t*>(&h0);
        u.y = *reinterpret_cast<uint32_t*>(&h1);
        ((uint2*)out)[i] = u;
    }
}

// 4 weights transposed in one launch (z picks the matrix)
__global__ void wtrh4(const float* __restrict__ i0, const float* __restrict__ i1,
                      const float* __restrict__ i2, const float* __restrict__ i3,
                      __half* __restrict__ o0, __half* __restrict__ o1,
                      __half* __restrict__ o2, __half* __restrict__ o3) {
    const float* in  = (blockIdx.z == 0) ? i0 : (blockIdx.z == 1) ? i1
                     : (blockIdx.z == 2) ? i2 : i3;
    __half* out      = (blockIdx.z == 0) ? o0 : (blockIdx.z == 1) ? o1
                     : (blockIdx.z == 2) ? o2 : o3;
    __shared__ float t[32][33];
    int bx = blockIdx.x << 5, by = blockIdx.y << 5;
#pragma unroll
    for (int i = 0; i < 4; i++) {
        int k = by + threadIdx.y + (i << 3);
        t[threadIdx.y + (i << 3)][threadIdx.x] = in[(size_t)k * HIDs + bx + threadIdx.x];
    }
    __syncthreads();
#pragma unroll
    for (int i = 0; i < 4; i++) {
        int n = bx + threadIdx.y + (i << 3);
        out[(size_t)n * HIDs + by + threadIdx.x] =
            __float2half(t[threadIdx.x][threadIdx.y + (i << 3)]);
    }
}

// v[b][s][h*128+d] -> vt[bh][d][s]
__global__ void vtrans(const __half* __restrict__ v, __half* __restrict__ vt) {
    __shared__ __half t[32][33];
    int bh = blockIdx.z;
    int b = bh >> 4, h = bh & 15;
    int s0 = blockIdx.x << 5, d0 = blockIdx.y << 5;
#pragma unroll
    for (int i = 0; i < 4; i++) {
        int s = s0 + threadIdx.y + (i << 3);
        t[threadIdx.y + (i << 3)][threadIdx.x] =
            v[((size_t)(b * Ssz + s)) * HIDs + h * HDd + d0 + threadIdx.x];
    }
    __syncthreads();
#pragma unroll
    for (int i = 0; i < 4; i++) {
        int d = d0 + threadIdx.y + (i << 3);
        vt[((size_t)bh * HDd + d) * Ssz + s0 + threadIdx.x] =
            t[threadIdx.x][threadIdx.y + (i << 3)];
    }
}

// ------------- fp16 GEMM 256x128: C = A[M,K] @ Bt[N,K]^T (+bias) -------------
// 256 threads, 8 warps (4 m x 2 n), warp tile 64x64, BK=32, 4-stage cp.async.
#define GST 40
#define G3_STAGE_H ((256+128)*GST)      // 15360 halfs / stage
#define G3_SMEM (4*G3_STAGE_H*2)        // 122880 B

__global__ __launch_bounds__(256, 1)
void tgemm_h3(const __half* __restrict__ A, const __half* __restrict__ Bt,
              const float* __restrict__ bias, void* __restrict__ Cout, int out_half)
{
    extern __shared__ __half gsm[];
    uint32_t smb = smem_u32(gsm);
    const int tid = threadIdx.x;
    const int wid = tid >> 5, lane = tid & 31;
    const int lr = lane >> 2, lc = lane & 3;
    const int bm = blockIdx.y << 8, bn = blockIdx.x << 7;
    const int wm = (wid & 3) << 6, wn = (wid >> 2) << 6;

    float acc[4][8][4];
#pragma unroll
    for (int im = 0; im < 4; im++)
#pragma unroll
        for (int jn = 0; jn < 8; jn++)
#pragma unroll
            for (int t = 0; t < 4; t++) acc[im][jn][t] = 0.f;

#define GLOAD3(st, ch)                                                         \
    {                                                                          \
        uint32_t ab = smb + (st) * (G3_STAGE_H * 2);                           \
        uint32_t bb = ab + 256 * GST * 2;                                      \
        _Pragma("unroll")                                                      \
        for (int i = 0; i < 4; i++) {                                          \
            int idx = tid + (i << 8);                                          \
            int r = idx >> 2, c = idx & 3;                                     \
            cp16(ab + r * 80 + c * 16,                                         \
                 A + (size_t)(bm + r) * HIDs + (ch) * 32 + c * 8);             \
        }                                                                      \
        _Pragma("unroll")                                                      \
        for (int i = 0; i < 2; i++) {                                          \
            int idx = tid + (i << 8);                                          \
            int r = idx >> 2, c = idx & 3;                                     \
            cp16(bb + r * 80 + c * 16,                                         \
                 Bt + (size_t)(bn + r) * HIDs + (ch) * 32 + c * 8);            \
        }                                                                      \
        asm volatile("cp.async.commit_group;");                                \
    }

    GLOAD3(0, 0);
    GLOAD3(1, 1);
    GLOAD3(2, 2);

    for (int it = 0; it < 64; it++) {
        asm volatile("cp.async.wait_group 2;");
        __syncthreads();
        if (it + 3 < 64) {
            GLOAD3((it + 3) & 3, it + 3);
        } else {
            asm volatile("cp.async.commit_group;");
        }

        const __half* as = gsm + (it & 3) * G3_STAGE_H;
        const __half* bs = as + 256 * GST;
#pragma unroll
        for (int kk = 0; kk < 2; kk++) {
            const int kc = (kk << 4) + (lc << 1);
            uint32_t af[4][4];
#pragma unroll
            for (int im = 0; im < 4; im++) {
                int m = wm + (im << 4) + lr;
                af[im][0] = *(const uint32_t*)(as + m * GST + kc);
                af[im][1] = *(const uint32_t*)(as + (m + 8) * GST + kc);
                af[im][2] = *(const uint32_t*)(as + m * GST + kc + 8);
                af[im][3] = *(const uint32_t*)(as + (m + 8) * GST + kc + 8);
            }
#pragma unroll
            for (int jn = 0; jn < 8; jn++) {
                int n = wn + (jn << 3) + lr;
                uint32_t bf[2];
                bf[0] = *(const uint32_t*)(bs + n * GST + kc);
                bf[1] = *(const uint32_t*)(bs + n * GST + kc + 8);
#pragma unroll
                for (int im = 0; im < 4; im++) mma16(acc[im][jn], af[im], bf);
            }
        }
    }
#undef GLOAD3

#pragma unroll
    for (int im = 0; im < 4; im++) {
        int row = bm + wm + (im << 4) + lr;
#pragma unroll
        for (int jn = 0; jn < 8; jn++) {
            int col = bn + wn + (jn << 3) + (lc << 1);
            float b0 = bias ? bias[col] : 0.f;
            float b1 = bias ? bias[col + 1] : 0.f;
            float v0 = acc[im][jn][0] + b0, v1 = acc[im][jn][1] + b1;
            float v2 = acc[im][jn][2] + b0, v3 = acc[im][jn][3] + b1;
            if (out_half) {
                __half* C = (__half*)Cout;
                *(__half2*)(C + (size_t)row * HIDs + col) = __floats2half2_rn(v0, v1);
                *(__half2*)(C + (size_t)(row + 8) * HIDs + col) = __floats2half2_rn(v2, v3);
            } else {
                float* C = (float*)Cout;
                *(float2*)(C + (size_t)row * HIDs + col) = make_float2(v0, v1);
                *(float2*)(C + (size_t)(row + 8) * HIDs + col) = make_float2(v2, v3);
            }
        }
    }
}

// ---------------- RoPE (q also pre-scaled by 128^-0.5) ----------------
__global__ void rope_h(__half* __restrict__ q, __half* __restrict__ k,
                       const int* __restrict__ positions)
{
    int idx = blockIdx.x * blockDim.x + threadIdx.x;
    if (idx >= Mrows * NHh * 64) return;
    int d = idx & 63;
    int t = idx >> 6;
    int h = t % NHh;
    int m = t / NHh;
    const float SC = 0.08838834764831845f;

    float pos = (float)positions[m];
    float invf = powf(10000.0f, -(float)d * (1.0f / 64.0f));
    float fr = pos * invf;
    float c = cosf(fr), s = sinf(fr);

    size_t base = (size_t)m * HIDs + h * HDd;
    float q1 = __half2float(q[base + d]), q2 = __half2float(q[base + 64 + d]);
    q[base + d]      = __float2half((q1 * c - q2 * s) * SC);
    q[base + 64 + d] = __float2half((q2 * c + q1 * s) * SC);
    float k1 = __half2float(k[base + d]), k2 = __half2float(k[base + 64 + d]);
    k[base + d]      = __float2half(k1 * c - k2 * s);
    k[base + 64 + d] = __float2half(k2 * c + k1 * s);
}

// ---------------- flash attention fp16, double-buffered K/V ----------------
// CTA = (b,h, 128 q rows), 8 warps x m16, k-tile 64,
// l via ones-column (17th n-tile of V^T). Ps reuses Q staging region.
#define QS_OFF 0                       // Q staging 128 x 136; then Ps 128 x 72
#define KS_OFF 17408
#define KBUF   8704                    // 64 x 136
#define VT_OFF 34816
#define VBUF   9792                    // 136 x 72
#define F_HALFS 54400                  // 108800 B

__global__ __launch_bounds__(256, 1)
void flash_h(const __half* __restrict__ Q, const __half* __restrict__ K,
             const __half* __restrict__ Vt, __half* __restrict__ O)
{
    extern __shared__ __half fsm[];
    __half* Qs = fsm;
    __half* Ps = fsm;
    uint32_t smb = smem_u32(fsm);

    const int tid = threadIdx.x;
    const int wid = tid >> 5, lane = tid & 31;
    const int lr = lane >> 2, lc = lane & 3;
    const int bh = blockIdx.y, b = bh >> 4, h = bh & 15;
    const int q0 = blockIdx.x << 7;
    const int wrow = wid << 4;
    const int nkt = (q0 >> 6) + 2;
    const float L2E = 1.44269504f;
    const size_t qbase = (size_t)(b * Ssz) * HIDs + (size_t)h * HDd;
    const size_t vtbase = (size_t)bh * HDd * Ssz;

    // ones/zeros rows 128..135 in BOTH V buffers (loads only touch rows 0..127)
    for (int i = tid; i < 2 * 8 * 72; i += 256) {
        int bufi = i / (8 * 72);
        int rem = i % (8 * 72);
        int rr = rem / 72, cc = rem % 72;
        fsm[VT_OFF + bufi * VBUF + (128 + rr) * 72 + cc] =
            (rr == 0 && cc < 64) ? __float2half(1.f) : __float2half(0.f);
    }

    // stage Q
#pragma unroll
    for (int i = 0; i < 8; i++) {
        int idx = tid + (i << 8);
        int r = idx >> 4, c = idx & 15;
        cp16(smb + r * 272 + c * 16, Q + qbase + (size_t)(q0 + r) * HIDs + c * 8);
    }
    asm volatile("cp.async.commit_group;");
    asm volatile("cp.async.wait_group 0;");
    __syncthreads();

    uint32_t qf[8][4];
#pragma unroll
    for (int kk = 0; kk < 8; kk++) {
        int r0 = wrow + lr;
        int c0 = (kk << 4) + (lc << 1);
        qf[kk][0] = *(const uint32_t*)(Qs + r0 * 136 + c0);
        qf[kk][1] = *(const uint32_t*)(Qs + (r0 + 8) * 136 + c0);
        qf[kk][2] = *(const uint32_t*)(Qs + r0 * 136 + c0 + 8);
        qf[kk][3] = *(const uint32_t*)(Qs + (r0 + 8) * 136 + c0 + 8);
    }

    // preload kt=0 into buffer 0
#pragma unroll
    for (int i = 0; i < 4; i++) {
        int idx = tid + (i << 8);
        int r = idx >> 4, c = idx & 15;
        cp16(smb + KS_OFF * 2 + r * 272 + c * 16,
             K + qbase + (size_t)r * HIDs + c * 8);
        int r2 = idx >> 3, c2 = idx & 7;
        cp16(smb + VT_OFF * 2 + r2 * 144 + c2 * 16,
             Vt + vtbase + (size_t)r2 * Ssz + c2 * 8);
    }
    asm volatile("cp.async.commit_group;");

    float oacc[17][4];
#pragma unroll
    for (int nt = 0; nt < 17; nt++)
#pragma unroll
        for (int t = 0; t < 4; t++) oacc[nt][t] = 0.f;
    float m0 = -1e30f, m1 = -1e30f;

    for (int kt = 0; kt < nkt; kt++) {
        const int buf = kt & 1;
        __syncthreads();   // prior compute on buf^1 finished; ones/Q reads done
        if (kt + 1 < nkt) {
            const int nb = buf ^ 1;
            const int k0n = (kt + 1) << 6;
#pragma unroll
            for (int i = 0; i < 4; i++) {
                int idx = tid + (i << 8);
                int r = idx >> 4, c = idx & 15;
                cp16(smb + (KS_OFF + nb * KBUF) * 2 + r * 272 + c * 16,
                     K + qbase + (size_t)(k0n + r) * HIDs + c * 8);
                int r2 = idx >> 3, c2 = idx & 7;
                cp16(smb + (VT_OFF + nb * VBUF) * 2 + r2 * 144 + c2 * 16,
                     Vt + vtbase + (size_t)r2 * Ssz + k0n + c2 * 8);
            }
        }
        asm volatile("cp.async.commit_group;");
        if (kt + 1 < nkt) asm volatile("cp.async.wait_group 1;");
        else              asm volatile("cp.async.wait_group 0;");
        __syncthreads();

        const __half* Ks = fsm + KS_OFF + buf * KBUF;
        const __half* Vs = fsm + VT_OFF + buf * VBUF;
        const int k0 = kt << 6;

        // S = Q K^T : m16 x n64 x k128
        float sacc[8][4];
#pragma unroll
        for (int jn = 0; jn < 8; jn++)
#pragma unroll
            for (int t = 0; t < 4; t++) sacc[jn][t] = 0.f;
#pragma unroll
        for (int kk = 0; kk < 8; kk++) {
            const int kc = (kk << 4) + (lc << 1);
#pragma unroll
            for (int jn = 0; jn < 8; jn++) {
                int n = (jn << 3) + lr;
                uint32_t bf[2];
                bf[0] = *(const uint32_t*)(Ks + n * 136 + kc);
                bf[1] = *(const uint32_t*)(Ks + n * 136 + kc + 8);
                mma16(sacc[jn], qf[kk], bf);
            }
        }

        // causal mask
        const int rg0 = q0 + wrow + lr;
        if (k0 + 63 > q0 + wrow) {
#pragma unroll
            for (int jn = 0; jn < 8; jn++) {
                int cg = k0 + (jn << 3) + (lc << 1);
                if (cg > rg0)         sacc[jn][0] = -1e30f;
                if (cg + 1 > rg0)     sacc[jn][1] = -1e30f;
                if (cg > rg0 + 8)     sacc[jn][2] = -1e30f;
                if (cg + 1 > rg0 + 8) sacc[jn][3] = -1e30f;
            }
        }

        // row max
        float mx0 = -1e30f, mx1 = -1e30f;
#pragma unroll
        for (int jn = 0; jn < 8; jn++) {
            mx0 = fmaxf(mx0, fmaxf(sacc[jn][0], sacc[jn][1]));
            mx1 = fmaxf(mx1, fmaxf(sacc[jn][2], sacc[jn][3]));
        }
        mx0 = fmaxf(mx0, __shfl_xor_sync(0xffffffffu, mx0, 1));
        mx0 = fmaxf(mx0, __shfl_xor_sync(0xffffffffu, mx0, 2));
        mx1 = fmaxf(mx1, __shfl_xor_sync(0xffffffffu, mx1, 1));
        mx1 = fmaxf(mx1, __shfl_xor_sync(0xffffffffu, mx1, 2));

        if (mx0 > m0 || mx1 > m1) {
            float mn0 = fmaxf(m0, mx0), mn1 = fmaxf(m1, mx1);
            float cf0 = exp2f((m0 - mn0) * L2E);
            float cf1 = exp2f((m1 - mn1) * L2E);
#pragma unroll
            for (int nt = 0; nt < 17; nt++) {
                oacc[nt][0] *= cf0; oacc[nt][1] *= cf0;
                oacc[nt][2] *= cf1; oacc[nt][3] *= cf1;
            }
            m0 = mn0; m1 = mn1;
        }

        // P = exp2((s-m)*log2e) via f16x2 MUFU, straight to smem (Ps stride 72)
        const float mls0 = m0 * L2E, mls1 = m1 * L2E;
        const int pr = wrow + lr;
#pragma unroll
        for (int jn = 0; jn < 8; jn++) {
            int pc = (jn << 3) + (lc << 1);
            uint32_t p01 = ex2h2(fmaf(sacc[jn][0], L2E, -mls0),
                                 fmaf(sacc[jn][1], L2E, -mls0));
            uint32_t p23 = ex2h2(fmaf(sacc[jn][2], L2E, -mls1),
                                 fmaf(sacc[jn][3], L2E, -mls1));
            *(uint32_t*)(Ps + pr * 72 + pc) = p01;
            *(uint32_t*)(Ps + (pr + 8) * 72 + pc) = p23;
        }
        __syncwarp();

        // O += P V^T : m16 x n136 x k64 (n-tile 16 accumulates l)
#pragma unroll
        for (int kk = 0; kk < 4; kk++) {
            const int kc = (kk << 4) + (lc << 1);
            uint32_t af[4];
            af[0] = *(const uint32_t*)(Ps + pr * 72 + kc);
            af[1] = *(const uint32_t*)(Ps + (pr + 8) * 72 + kc);
            af[2] = *(const uint32_t*)(Ps + pr * 72 + kc + 8);
            af[3] = *(const uint32_t*)(Ps + (pr + 8) * 72 + kc + 8);
#pragma unroll
            for (int nt = 0; nt < 17; nt++) {
                int n = (nt << 3) + lr;
                uint32_t bf[2];
                bf[0] = *(const uint32_t*)(Vs + n * 72 + kc);
                bf[1] = *(const uint32_t*)(Vs + n * 72 + kc + 8);
                mma16(oacc[nt], af, bf);
            }
        }
    }

    // l lives in oacc[16][0]/[2] at the lc==0 lane of each quad
    float l0 = __shfl_sync(0xffffffffu, oacc[16][0], lane & 28);
    float l1 = __shfl_sync(0xffffffffu, oacc[16][2], lane & 28);
    float i0 = 1.f / l0, i1 = 1.f / l1;
    const int row = q0 + wrow + lr;
#pragma unroll
    for (int nt = 0; nt < 16; nt++) {
        int col = (nt << 3) + (lc << 1);
        *(__half2*)(O + qbase + (size_t)row * HIDs + col) =
            __floats2half2_rn(oacc[nt][0] * i0, oacc[nt][1] * i0);
        *(__half2*)(O + qbase + (size_t)(row + 8) * HIDs + col) =
            __floats2half2_rn(oacc[nt][2] * i1, oacc[nt][3] * i1);
    }
}

// ---------------------------------------------------------------------------
extern "C" void kernel_launch(void* const* d_in, const int* in_sizes, int n_in,
                              void* d_out, int out_size)
{
    (void)in_sizes; (void)n_in; (void)out_size;
    const float* hidden    = (const float*)d_in[0];
    const int*   positions = (const int*)  d_in[1];
    const float* wq = (const float*)d_in[2];
    const float* bq = (const float*)d_in[3];
    const float* wk = (const float*)d_in[4];
    const float* bk = (const float*)d_in[5];
    const float* wv = (const float*)d_in[6];
    const float* bv = (const float*)d_in[7];
    const float* wc = (const float*)d_in[8];
    float* out = (float*)d_out;

    __half *hp, *qp, *kp, *vp, *vtp, *ap, *wqp, *wkp, *wvp, *wcp;
    cudaGetSymbolAddress((void**)&hp,  g_hid);
    cudaGetSymbolAddress((void**)&qp,  g_q);
    cudaGetSymbolAddress((void**)&kp,  g_k);
    cudaGetSymbolAddress((void**)&vp,  g_v);
    cudaGetSymbolAddress((void**)&vtp, g_vt);
    cudaGetSymbolAddress((void**)&ap,  g_attn);
    cudaGetSymbolAddress((void**)&wqp, g_wq);
    cudaGetSymbolAddress((void**)&wkp, g_wk);
    cudaGetSymbolAddress((void**)&wvp, g_wv);
    cudaGetSymbolAddress((void**)&wcp, g_wc);

    cvth<<<(Mrows*HIDs/4 + 255)/256, 256>>>(hidden, hp, Mrows*HIDs/4);
    wtrh4<<<dim3(HIDs/32, HIDs/32, 4), dim3(32, 8)>>>(wq, wk, wv, wc,
                                                      wqp, wkp, wvp, wcp);

    cudaFuncSetAttribute(tgemm_h3, cudaFuncAttributeMaxDynamicSharedMemorySize, G3_SMEM);
    dim3 gg(HIDs / 128, Mrows / 256);   // (16, 16)
    tgemm_h3<<<gg, 256, G3_SMEM>>>(hp, wqp, bq, qp, 1);
    tgemm_h3<<<gg, 256, G3_SMEM>>>(hp, wkp, bk, kp, 1);
    tgemm_h3<<<gg, 256, G3_SMEM>>>(hp, wvp, bv, vp, 1);

    rope_h<<<(Mrows * NHh * 64) / 256, 256>>>(qp, kp, positions);
    vtrans<<<dim3(Ssz/32, HDd/32, Bsz*NHh), dim3(32, 8)>>>(vp, vtp);

    cudaFuncSetAttribute(flash_h, cudaFuncAttributeMaxDynamicSharedMemorySize,
                         F_HALFS * 2);
    flash_h<<<dim3(Ssz / 128, Bsz * NHh), 256, F_HALFS * 2>>>(qp, kp, vtp, ap);

    tgemm_h3<<<gg, 256, G3_SMEM>>>(ap, wcp, nullptr, out, 0);
}